// round 15
// baseline (speedup 1.0000x reference)
#include <cuda_runtime.h>
#include <cuda_fp16.h>
#include <stdint.h>

#define CIn 512
#define COc 256
#define NB  16

// ---------------- device scratch (allocation-free) --------------------------
__device__ __half g_xh [NB * 784 * CIn];       // x channel-last, fp16
__device__ __half g_t1h[NB * 3136 * COc];      // t1 channel-last, fp16
__device__ float  g_scf[NB * COc * 3136];      // shortcut, NCHW fp32
__device__ __half g_wA [25 * 32 * 4 * 2048];   // frag-order weights (fp16)
__device__ __half g_wB [9 * 16 * 2 * 2048];

// ---------------- smem stage layout (K=32 per stage) ------------------------
// A [0, 10240) : 128 rows x 64B data in 80B stride
// B [10240, 18432) : 2 x 4096 (k16-major)
#define BOFF 10240
#define STAGE_BYTES 18432
#define NSTAGE 6
#define MBAR_OFF (NSTAGE * STAGE_BYTES)        // 110592
#define SMEM_BYTES (MBAR_OFF + 128)

// ---------------- helpers ---------------------------------------------------
__device__ __forceinline__ uint32_t smem_u32(const void* p) {
    uint32_t a;
    asm("{ .reg .u64 t; cvta.to.shared.u64 t, %1; cvt.u32.u64 %0, t; }"
        : "=r"(a) : "l"(p));
    return a;
}
__device__ __forceinline__ void cpa16(uint32_t dst, const void* src, int srcsize) {
    asm volatile("cp.async.cg.shared.global [%0], [%1], 16, %2;"
                 :: "r"(dst), "l"(src), "r"(srcsize));
}
__device__ __forceinline__ void mb_init(uint32_t a, uint32_t cnt) {
    asm volatile("mbarrier.init.shared.b64 [%0], %1;" :: "r"(a), "r"(cnt) : "memory");
}
__device__ __forceinline__ void mb_arrive(uint32_t a) {
    asm volatile("{\n\t.reg .b64 t;\n\tmbarrier.arrive.shared.b64 t, [%0];\n\t}"
                 :: "r"(a) : "memory");
}
__device__ __forceinline__ void cp_arrive(uint32_t a) {
    asm volatile("cp.async.mbarrier.arrive.noinc.shared.b64 [%0];" :: "r"(a) : "memory");
}
__device__ __forceinline__ void mb_wait(uint32_t a, uint32_t par) {
    asm volatile(
        "{\n\t.reg .pred P;\n\t"
        "WL_%=:\n\t"
        "mbarrier.try_wait.parity.shared.b64 P, [%0], %1, 0x989680;\n\t"
        "@P bra.uni WD_%=;\n\t"
        "bra.uni WL_%=;\n\t"
        "WD_%=:\n\t}"
        :: "r"(a), "r"(par) : "memory");
}
__device__ __forceinline__ void mma16816h(float* c, const uint32_t* a, const uint32_t* b) {
    asm volatile(
        "mma.sync.aligned.m16n8k16.row.col.f32.f16.f16.f32 "
        "{%0,%1,%2,%3},{%4,%5,%6,%7},{%8,%9},{%0,%1,%2,%3};"
        : "+f"(c[0]), "+f"(c[1]), "+f"(c[2]), "+f"(c[3])
        : "r"(a[0]), "r"(a[1]), "r"(a[2]), "r"(a[3]), "r"(b[0]), "r"(b[1]));
}
__device__ __forceinline__ int bfrag_idx(int nf, int n, int kk) {
    int lane = n * 4 + ((kk & 7) >> 1);
    return nf * 128 + lane * 4 + (kk >> 3) * 2 + (kk & 1);
}

// ---------------- fused prep: channel-last fp16 x + frag-order weights ------
#define NXBLK 6400
__global__ void prep_all(const float* __restrict__ x,  const float* __restrict__ w1,
                         const float* __restrict__ wsc, const float* __restrict__ w2)
{
    __shared__ float tile[32][33];
    if (blockIdx.x < NXBLK) {
        int bid = blockIdx.x;
        int st  = (bid % 25) * 32;
        int cib = ((bid / 25) & 15) * 32;
        int b   = bid / 400;
        const int tx = threadIdx.x & 31, ty = threadIdx.x >> 5;
#pragma unroll
        for (int i = 0; i < 4; ++i) {
            int ci = i * 8 + ty;
            int s  = st + tx;
            float v = 0.f;
            if (s < 784) v = x[(b * CIn + cib + ci) * 784 + s];
            tile[ci][tx] = v;
        }
        __syncthreads();
#pragma unroll
        for (int i = 0; i < 4; ++i) {
            int s = st + i * 8 + ty;
            if (s < 784)
                g_xh[(b * 784 + s) * CIn + cib + tx] = __float2half(tile[tx][i * 8 + ty]);
        }
    } else {
        int idx = (blockIdx.x - NXBLK) * 256 + threadIdx.x;
        const int nA  = 25 * CIn * 512;
        const int nBw = 9 * COc * COc;
        if (idx < nA) {
            int tap = idx % 25, rest = idx / 25;
            int ci = rest & 511, oc = rest >> 9;
            float v = (oc < COc) ? w1[(oc * CIn + ci) * 25 + tap]
                                 : wsc[((oc - COc) * CIn + ci) * 25 + tap];
            int e = ((tap * 32 + (ci >> 4)) * 4 + (oc >> 7)) * 2048
                  + bfrag_idx((oc & 127) >> 3, oc & 7, ci & 15);
            g_wA[e] = __float2half(v);
        }
        if (idx < nBw) {
            int tap = idx % 9, rest = idx / 9;
            int ci = rest & 255, oc = rest >> 8;
            float v = w2[(oc * COc + ci) * 9 + tap];
            int e = ((tap * 16 + (ci >> 4)) * 2 + (oc >> 7)) * 2048
                  + bfrag_idx((oc & 127) >> 3, oc & 7, ci & 15);
            g_wB[e] = __float2half(v);
        }
    }
}

// ---------------- MMA on one ready stage (staggered phase order) ------------
#define MMA_STAGE(SB)                                                           \
{                                                                               \
    _Pragma("unroll")                                                           \
    for (int si = 0; si < 2; ++si) {                                            \
        const int s_ = (si + (wid & 1)) & 1;                                    \
        uint32_t bh[4][2];                                                      \
        _Pragma("unroll")                                                       \
        for (int nfl = 0; nfl < 4; ++nfl) {                                     \
            uint32_t ba = (SB) + BOFF + s_ * 4096u + (wn * 4 + nfl) * 256u + lane * 8u; \
            asm volatile("ld.shared.v2.b32 {%0,%1}, [%2];"                      \
                : "=r"(bh[nfl][0]), "=r"(bh[nfl][1]) : "r"(ba));                \
        }                                                                       \
        _Pragma("unroll")                                                       \
        for (int mi = 0; mi < 4; ++mi) {                                        \
            const int mfl = (mi + wid) & 3;                                     \
            uint32_t aa = (SB) + (wm * 64 + mfl * 16 + (lane & 15)) * 80u       \
                        + (s_ * 2 + (lane >> 4)) * 16u;                         \
            uint32_t ah[4];                                                     \
            asm volatile("ldmatrix.sync.aligned.m8n8.x4.shared.b16 {%0,%1,%2,%3}, [%4];" \
                : "=r"(ah[0]), "=r"(ah[1]), "=r"(ah[2]), "=r"(ah[3]) : "r"(aa)); \
            _Pragma("unroll")                                                   \
            for (int nfl = 0; nfl < 4; ++nfl)                                   \
                mma16816h(acc[mfl][nfl], ah, bh[nfl]);                          \
        }                                                                       \
    }                                                                           \
}

// mbar addresses: full[s] = mb + s*16, empty[s] = mb + s*16 + 8
#define FULLB(s)  (mb + (uint32_t)(s) * 16u)
#define EMPTYB(s) (mb + (uint32_t)(s) * 16u + 8u)

// ---------------- chunk issue: convA ----------------------------------------
__device__ __forceinline__ void issueA(uint32_t sb, int cc, int m0, int ntile,
                                       int ph, int pw, int nTb, int tid)
{
    int tapi = cc >> 4, kc = cc & 15;
    int ta, tb;
    if (nTb == 2) { ta = tapi >> 1; tb = tapi & 1; }
    else          { ta = tapi / 3;  tb = tapi % 3; }
    int da = ph ? ta : ta - 1;
    int db = pw ? tb : tb - 1;
    int tap = (ph ? 2 * ta + 1 : 2 * ta) * 5 + (pw ? 2 * tb + 1 : 2 * tb);

    if (tid < 128) {
        int m = m0 + tid;
        int b = m / 784, sp = m - b * 784;
        int i = sp / 28, j = sp - i * 28;
        int y = i + da, xx = j + db;
        bool valid = ((unsigned)y < 28u) && ((unsigned)xx < 28u);
        const __half* src = g_xh + (valid ? ((b * 784 + y * 28 + xx) * CIn + kc * 32) : 0);
        int ss = valid ? 16 : 0;
        uint32_t abase = sb + (uint32_t)tid * 80u;
#pragma unroll
        for (int c4 = 0; c4 < 4; ++c4) cpa16(abase + c4 * 16u, src + c4 * 8, ss);
    }
#pragma unroll
    for (int c4 = 0; c4 < 2; ++c4) {
        int q = tid * 2 + c4;                 // 0..511
        int s = q >> 8, qq = q & 255;
        int img = (tap * 32 + kc * 2 + s) * 4 + ntile;
        cpa16(sb + BOFF + s * 4096u + qq * 16u, g_wA + img * 2048 + qq * 8, 16);
    }
}

// ---------------- chunk issue: convB ----------------------------------------
__device__ __forceinline__ void issueB(uint32_t sb, int cc, int m0, int ntile, int tid)
{
    int tapi = cc >> 3, kc = cc & 7;
    int da = tapi / 3 - 1, db = tapi % 3 - 1;

    if (tid < 128) {
        int m = m0 + tid;
        int b = m / 3136, sp = m - b * 3136;
        int i = sp / 56, j = sp - i * 56;
        int y = i + da, xx = j + db;
        bool valid = ((unsigned)y < 56u) && ((unsigned)xx < 56u);
        const __half* src = g_t1h + (valid ? ((b * 3136 + y * 56 + xx) * COc + kc * 32) : 0);
        int ss = valid ? 16 : 0;
        uint32_t abase = sb + (uint32_t)tid * 80u;
#pragma unroll
        for (int c4 = 0; c4 < 4; ++c4) cpa16(abase + c4 * 16u, src + c4 * 8, ss);
    }
#pragma unroll
    for (int c4 = 0; c4 < 2; ++c4) {
        int q = tid * 2 + c4;
        int s = q >> 8, qq = q & 255;
        int img = (tapi * 16 + kc * 2 + s) * 2 + ntile;
        cpa16(sb + BOFF + s * 4096u + qq * 16u, g_wB + img * 2048 + qq * 8, 16);
    }
}

// ---------------- GEMM A: conv1 / shortcut ----------------------------------
__global__ __launch_bounds__(256, 2)
void convA_mma(const float* __restrict__ g1, const float* __restrict__ b1,
               const float* __restrict__ m1, const float* __restrict__ v1,
               const float* __restrict__ gs, const float* __restrict__ bs,
               const float* __restrict__ ms, const float* __restrict__ vs)
{
    extern __shared__ __align__(16) uint8_t dsm[];
    const uint32_t sb0 = smem_u32(dsm);
    const uint32_t mb  = sb0 + MBAR_OFF;
    const int tid = threadIdx.x, lane = tid & 31, wid = tid >> 5;
    const int wm = wid >> 2, wn = wid & 3;
    const int m0 = blockIdx.x * 128, ntile = blockIdx.y;
    const int par = blockIdx.z;
    const int ph = par >> 1, pw = par & 1;
    const int nTa = ph ? 2 : 3, nTb = pw ? 2 : 3;
    const int C = nTa * nTb * 16;

    if (tid < NSTAGE) { mb_init(FULLB(tid), 256); mb_init(EMPTYB(tid), 256); }
    __syncthreads();

    float acc[4][4][4];
#pragma unroll
    for (int a = 0; a < 4; ++a)
#pragma unroll
        for (int b = 0; b < 4; ++b)
#pragma unroll
            for (int e = 0; e < 4; ++e) acc[a][b][e] = 0.f;

    // prologue: fill stages 0..2
#pragma unroll
    for (int p = 0; p < 3; ++p) {
        issueA(sb0 + p * STAGE_BYTES, p, m0, ntile, ph, pw, nTb, tid);
        cp_arrive(FULLB(p));
    }

    int s = 0, pf = 0;        // stage/parity of chunk being consumed
    int s2 = 3, pe = 1;       // stage/parity for empty-wait of chunk being issued
    for (int cc = 0; cc < C; ++cc) {
        int c2 = cc + 3;
        if (c2 < C) {
            if (c2 >= NSTAGE) mb_wait(EMPTYB(s2), pe);
            issueA(sb0 + s2 * STAGE_BYTES, c2, m0, ntile, ph, pw, nTb, tid);
            cp_arrive(FULLB(s2));
            if (++s2 == NSTAGE) { s2 = 0; pe ^= 1; }
        }
        mb_wait(FULLB(s), pf);
        const uint32_t SBc = sb0 + s * STAGE_BYTES;
        MMA_STAGE(SBc)
        mb_arrive(EMPTYB(s));
        if (++s == NSTAGE) { s = 0; pf ^= 1; }
    }
    __syncthreads();

    const int n0 = ntile * 128;
    if (ntile < 2) {
        // ---- t1 branch: BN + ReLU, store single fp16, channel-last ----------
        float es[4][2], eb[4][2];
#pragma unroll
        for (int nfl = 0; nfl < 4; ++nfl)
#pragma unroll
            for (int t = 0; t < 2; ++t) {
                int oc = n0 + wn * 32 + nfl * 8 + 2 * (lane & 3) + t;
                float sv = g1[oc] * rsqrtf(v1[oc] + 1e-5f);
                es[nfl][t] = sv;
                eb[nfl][t] = b1[oc] - m1[oc] * sv;
            }
#pragma unroll
        for (int mfl = 0; mfl < 4; ++mfl)
#pragma unroll
            for (int eh = 0; eh < 2; ++eh) {
                int ml = wm * 64 + mfl * 16 + (lane >> 2) + 8 * eh;
                int m = m0 + ml;
                int b = m / 784, sp = m - b * 784;
                int i = sp / 28, j = sp - i * 28;
                int oh = 2 * i + ph, ow = 2 * j + pw;
                int base = (b * 3136 + oh * 56 + ow) * COc + n0 + wn * 32 + 2 * (lane & 3);
#pragma unroll
                for (int nfl = 0; nfl < 4; ++nfl) {
                    float v0 = fmaxf(acc[mfl][nfl][eh * 2 + 0] * es[nfl][0] + eb[nfl][0], 0.f);
                    float v1v = fmaxf(acc[mfl][nfl][eh * 2 + 1] * es[nfl][1] + eb[nfl][1], 0.f);
                    __half2 h2;
                    h2.x = __float2half(v0);
                    h2.y = __float2half(v1v);
                    *(__half2*)(g_t1h + base + nfl * 8) = h2;
                }
            }
    } else {
        // ---- shortcut branch: smem transpose, BN, NCHW scatter --------------
        float* stage = (float*)dsm;
        for (int p = 0; p < 2; ++p) {
            __syncthreads();
            if ((wn >> 1) == p) {
#pragma unroll
                for (int mfl = 0; mfl < 4; ++mfl)
#pragma unroll
                    for (int nfl = 0; nfl < 4; ++nfl)
#pragma unroll
                        for (int e = 0; e < 4; ++e) {
                            int nlrel = (wn & 1) * 32 + nfl * 8 + 2 * (lane & 3) + (e & 1);
                            int ml    = wm * 64 + mfl * 16 + (lane >> 2) + 8 * (e >> 1);
                            stage[nlrel * 132 + ml] = acc[mfl][nfl][e];
                        }
            }
            __syncthreads();
#pragma unroll
            for (int rr = 0; rr < 8; ++rr) {
                int row = wid * 8 + rr;
                int c   = n0 - COc + p * 64 + row;
                float sv  = gs[c] * rsqrtf(vs[c] + 1e-5f);
                float ebv = bs[c] - ms[c] * sv;
                float4 f = *(const float4*)(stage + row * 132 + lane * 4);
                float fv[4] = {f.x, f.y, f.z, f.w};
#pragma unroll
                for (int q = 0; q < 4; ++q) {
                    int m = m0 + lane * 4 + q;
                    int b = m / 784, sp = m - b * 784;
                    int i = sp / 28, j = sp - i * 28;
                    int oh = 2 * i + ph, ow = 2 * j + pw;
                    g_scf[((b * COc + c) * 56 + oh) * 56 + ow] = fv[q] * sv + ebv;
                }
            }
        }
    }
}

// ---------------- GEMM B: conv2 + BN2 + shortcut + ReLU ---------------------
__global__ __launch_bounds__(256, 2)
void convB_mma(const float* __restrict__ g2, const float* __restrict__ b2,
               const float* __restrict__ m2, const float* __restrict__ v2,
               float* __restrict__ out)
{
    extern __shared__ __align__(16) uint8_t dsm[];
    const uint32_t sb0 = smem_u32(dsm);
    const uint32_t mb  = sb0 + MBAR_OFF;
    const int tid = threadIdx.x, lane = tid & 31, wid = tid >> 5;
    const int wm = wid >> 2, wn = wid & 3;
    const int m0 = blockIdx.x * 128, ntile = blockIdx.y;
    const int C = 72;

    if (tid < NSTAGE) { mb_init(FULLB(tid), 256); mb_init(EMPTYB(tid), 256); }
    __syncthreads();

    float acc[4][4][4];
#pragma unroll
    for (int a = 0; a < 4; ++a)
#pragma unroll
        for (int b = 0; b < 4; ++b)
#pragma unroll
            for (int e = 0; e < 4; ++e) acc[a][b][e] = 0.f;

#pragma unroll
    for (int p = 0; p < 3; ++p) {
        issueB(sb0 + p * STAGE_BYTES, p, m0, ntile, tid);
        cp_arrive(FULLB(p));
    }

    int s = 0, pf = 0;
    int s2 = 3, pe = 1;
    for (int cc = 0; cc < C; ++cc) {
        int c2 = cc + 3;
        if (c2 < C) {
            if (c2 >= NSTAGE) mb_wait(EMPTYB(s2), pe);
            issueB(sb0 + s2 * STAGE_BYTES, c2, m0, ntile, tid);
            cp_arrive(FULLB(s2));
            if (++s2 == NSTAGE) { s2 = 0; pe ^= 1; }
        }
        mb_wait(FULLB(s), pf);
        const uint32_t SBc = sb0 + s * STAGE_BYTES;
        MMA_STAGE(SBc)
        mb_arrive(EMPTYB(s));
        if (++s == NSTAGE) { s = 0; pf ^= 1; }
    }
    __syncthreads();

    float* stage = (float*)dsm;
    const int n0 = ntile * 128;
    for (int p = 0; p < 2; ++p) {
        __syncthreads();
        if ((wn >> 1) == p) {
#pragma unroll
            for (int mfl = 0; mfl < 4; ++mfl)
#pragma unroll
                for (int nfl = 0; nfl < 4; ++nfl)
#pragma unroll
                    for (int e = 0; e < 4; ++e) {
                        int nlrel = (wn & 1) * 32 + nfl * 8 + 2 * (lane & 3) + (e & 1);
                        int ml    = wm * 64 + mfl * 16 + (lane >> 2) + 8 * (e >> 1);
                        stage[nlrel * 132 + ml] = acc[mfl][nfl][e];
                    }
        }
        __syncthreads();
#pragma unroll
        for (int rr = 0; rr < 8; ++rr) {
            int row = wid * 8 + rr;
            int oc  = n0 + p * 64 + row;
            float sv = g2[oc] * rsqrtf(v2[oc] + 1e-5f);
            float eb = b2[oc] - m2[oc] * sv;
            int m = m0 + lane * 4;
            int b = m / 3136, sp = m - b * 3136;
            int idx = (b * COc + oc) * 3136 + sp;
            float4 f  = *(const float4*)(stage + row * 132 + lane * 4);
            float4 sc = *(const float4*)(g_scf + idx);
            float4 o;
            o.x = fmaxf(f.x * sv + eb + sc.x, 0.f);
            o.y = fmaxf(f.y * sv + eb + sc.y, 0.f);
            o.z = fmaxf(f.z * sv + eb + sc.z, 0.f);
            o.w = fmaxf(f.w * sv + eb + sc.w, 0.f);
            *(float4*)(out + idx) = o;
        }
    }
}

// ---------------------------------------------------------------------------
extern "C" void kernel_launch(void* const* d_in, const int* in_sizes, int n_in,
                              void* d_out, int out_size)
{
    const float* x   = (const float*)d_in[0];
    const float* w1  = (const float*)d_in[1];
    const float* g1  = (const float*)d_in[2];
    const float* b1  = (const float*)d_in[3];
    const float* m1  = (const float*)d_in[4];
    const float* v1  = (const float*)d_in[5];
    const float* w2  = (const float*)d_in[6];
    const float* g2  = (const float*)d_in[7];
    const float* b2  = (const float*)d_in[8];
    const float* m2  = (const float*)d_in[9];
    const float* v2  = (const float*)d_in[10];
    const float* wsc = (const float*)d_in[11];
    const float* gs  = (const float*)d_in[12];
    const float* bs  = (const float*)d_in[13];
    const float* ms  = (const float*)d_in[14];
    const float* vs  = (const float*)d_in[15];
    float* out = (float*)d_out;

    static int configured = 0;
    if (!configured) {
        cudaFuncSetAttribute(convA_mma, cudaFuncAttributeMaxDynamicSharedMemorySize, SMEM_BYTES);
        cudaFuncSetAttribute(convB_mma, cudaFuncAttributeMaxDynamicSharedMemorySize, SMEM_BYTES);
        configured = 1;
    }

    prep_all<<<NXBLK + 25600, 256>>>(x, w1, wsc, w2);

    dim3 gA(98, 4, 4);
    convA_mma<<<gA, 256, SMEM_BYTES>>>(g1, b1, m1, v1, gs, bs, ms, vs);

    dim3 gB(392, 2);
    convB_mma<<<gB, 256, SMEM_BYTES>>>(g2, b2, m2, v2, out);
}

// round 16
// speedup vs baseline: 6.4881x; 6.4881x over previous
#include <cuda_runtime.h>
#include <cuda_fp16.h>
#include <stdint.h>

#define CIn 512
#define COc 256
#define NB  16

// ---------------- device scratch (allocation-free) --------------------------
__device__ __half g_xh [NB * 784 * CIn];       // x channel-last, fp16
__device__ __half g_t1h[NB * 3136 * COc];      // t1 channel-last, fp16
__device__ float  g_scf[NB * COc * 3136];      // shortcut, NCHW fp32
__device__ __half g_wA [25 * 32 * 4 * 2048];   // frag-order weights (fp16)
__device__ __half g_wB [9 * 16 * 2 * 2048];

// ---------------- smem stage layout (K=32 per stage) ------------------------
// A [0, 10240) : 128 rows x 64B data in 80B stride
// B [10240, 18432) : 2 x 4096 (k16-major)
#define BOFF 10240
#define STAGE_BYTES 18432
#define NSTAGE 5
#define MBAR_OFF (NSTAGE * STAGE_BYTES)        // 92160
#define SMEM_BYTES (MBAR_OFF + 128)

// ---------------- helpers ---------------------------------------------------
__device__ __forceinline__ uint32_t smem_u32(const void* p) {
    uint32_t a;
    asm("{ .reg .u64 t; cvta.to.shared.u64 t, %1; cvt.u32.u64 %0, t; }"
        : "=r"(a) : "l"(p));
    return a;
}
__device__ __forceinline__ void cpa16(uint32_t dst, const void* src, int srcsize) {
    asm volatile("cp.async.cg.shared.global [%0], [%1], 16, %2;"
                 :: "r"(dst), "l"(src), "r"(srcsize));
}
__device__ __forceinline__ void mb_init(uint32_t a, uint32_t cnt) {
    asm volatile("mbarrier.init.shared.b64 [%0], %1;" :: "r"(a), "r"(cnt) : "memory");
}
__device__ __forceinline__ void mb_arrive(uint32_t a) {
    asm volatile("{\n\t.reg .b64 t;\n\tmbarrier.arrive.shared.b64 t, [%0];\n\t}"
                 :: "r"(a) : "memory");
}
__device__ __forceinline__ void cp_arrive(uint32_t a) {
    asm volatile("cp.async.mbarrier.arrive.noinc.shared.b64 [%0];" :: "r"(a) : "memory");
}
__device__ __forceinline__ void mb_wait(uint32_t a, uint32_t par) {
    uint32_t done;
    do {
        asm volatile(
            "{\n\t.reg .pred p;\n\t"
            "mbarrier.test_wait.parity.shared.b64 p, [%1], %2;\n\t"
            "selp.b32 %0, 1, 0, p;\n\t}"
            : "=r"(done) : "r"(a), "r"(par) : "memory");
        if (!done) __nanosleep(20);
    } while (!done);
}
__device__ __forceinline__ void mma16816h(float* c, const uint32_t* a, const uint32_t* b) {
    asm volatile(
        "mma.sync.aligned.m16n8k16.row.col.f32.f16.f16.f32 "
        "{%0,%1,%2,%3},{%4,%5,%6,%7},{%8,%9},{%0,%1,%2,%3};"
        : "+f"(c[0]), "+f"(c[1]), "+f"(c[2]), "+f"(c[3])
        : "r"(a[0]), "r"(a[1]), "r"(a[2]), "r"(a[3]), "r"(b[0]), "r"(b[1]));
}
__device__ __forceinline__ int bfrag_idx(int nf, int n, int kk) {
    int lane = n * 4 + ((kk & 7) >> 1);
    return nf * 128 + lane * 4 + (kk >> 3) * 2 + (kk & 1);
}

// ---------------- fused prep: channel-last fp16 x + frag-order weights ------
#define NXBLK 6400
__global__ void prep_all(const float* __restrict__ x,  const float* __restrict__ w1,
                         const float* __restrict__ wsc, const float* __restrict__ w2)
{
    __shared__ float tile[32][33];
    if (blockIdx.x < NXBLK) {
        int bid = blockIdx.x;
        int st  = (bid % 25) * 32;
        int cib = ((bid / 25) & 15) * 32;
        int b   = bid / 400;
        const int tx = threadIdx.x & 31, ty = threadIdx.x >> 5;
#pragma unroll
        for (int i = 0; i < 4; ++i) {
            int ci = i * 8 + ty;
            int s  = st + tx;
            float v = 0.f;
            if (s < 784) v = x[(b * CIn + cib + ci) * 784 + s];
            tile[ci][tx] = v;
        }
        __syncthreads();
#pragma unroll
        for (int i = 0; i < 4; ++i) {
            int s = st + i * 8 + ty;
            if (s < 784)
                g_xh[(b * 784 + s) * CIn + cib + tx] = __float2half(tile[tx][i * 8 + ty]);
        }
    } else {
        int idx = (blockIdx.x - NXBLK) * 256 + threadIdx.x;
        const int nA  = 25 * CIn * 512;
        const int nBw = 9 * COc * COc;
        if (idx < nA) {
            int tap = idx % 25, rest = idx / 25;
            int ci = rest & 511, oc = rest >> 9;
            float v = (oc < COc) ? w1[(oc * CIn + ci) * 25 + tap]
                                 : wsc[((oc - COc) * CIn + ci) * 25 + tap];
            int e = ((tap * 32 + (ci >> 4)) * 4 + (oc >> 7)) * 2048
                  + bfrag_idx((oc & 127) >> 3, oc & 7, ci & 15);
            g_wA[e] = __float2half(v);
        }
        if (idx < nBw) {
            int tap = idx % 9, rest = idx / 9;
            int ci = rest & 255, oc = rest >> 8;
            float v = w2[(oc * COc + ci) * 9 + tap];
            int e = ((tap * 16 + (ci >> 4)) * 2 + (oc >> 7)) * 2048
                  + bfrag_idx((oc & 127) >> 3, oc & 7, ci & 15);
            g_wB[e] = __float2half(v);
        }
    }
}

// ---------------- MMA on one ready stage (1-term fp16, K=32) ----------------
#define MMA_STAGE(SB)                                                           \
{                                                                               \
    _Pragma("unroll")                                                           \
    for (int s = 0; s < 2; ++s) {                                               \
        uint32_t bh[4][2];                                                      \
        _Pragma("unroll")                                                       \
        for (int nfl = 0; nfl < 4; ++nfl) {                                     \
            uint32_t ba = (SB) + BOFF + s * 4096u + (wn * 4 + nfl) * 256u + lane * 8u; \
            asm volatile("ld.shared.v2.b32 {%0,%1}, [%2];"                      \
                : "=r"(bh[nfl][0]), "=r"(bh[nfl][1]) : "r"(ba));                \
        }                                                                       \
        _Pragma("unroll")                                                       \
        for (int mfl = 0; mfl < 4; ++mfl) {                                     \
            uint32_t aa = (SB) + (wm * 64 + mfl * 16 + (lane & 15)) * 80u       \
                        + (s * 2 + (lane >> 4)) * 16u;                          \
            uint32_t ah[4];                                                     \
            asm volatile("ldmatrix.sync.aligned.m8n8.x4.shared.b16 {%0,%1,%2,%3}, [%4];" \
                : "=r"(ah[0]), "=r"(ah[1]), "=r"(ah[2]), "=r"(ah[3]) : "r"(aa)); \
            _Pragma("unroll")                                                   \
            for (int nfl = 0; nfl < 4; ++nfl)                                   \
                mma16816h(acc[mfl][nfl], ah, bh[nfl]);                          \
        }                                                                       \
    }                                                                           \
}

// mbar addresses: full[s] = mb + s*16, empty[s] = mb + s*16 + 8
#define FULLB(s)  (mb + (uint32_t)(s) * 16u)
#define EMPTYB(s) (mb + (uint32_t)(s) * 16u + 8u)

// Per-thread loop-invariant gather state
struct GInv {
    int pb;          // batch * spatial_size
    int pi, pj;      // spatial coords
    uint32_t a_off;  // A smem offset within stage (tid*80)
    int ws0, wq0;    // weight-copy slot 0
    int ws1, wq1;    // weight-copy slot 1
};

// ---------------- chunk issue: convA ----------------------------------------
__device__ __forceinline__ void issueA(uint32_t sb, int cc, const GInv& gi,
                                       int ntile, int ph, int pw, int nTb, int tid)
{
    int tapi = cc >> 4, kc = cc & 15;
    int ta, tb;
    if (nTb == 2) { ta = tapi >> 1; tb = tapi & 1; }
    else          { ta = tapi / 3;  tb = tapi % 3; }
    int da = ph ? ta : ta - 1;
    int db = pw ? tb : tb - 1;
    int tap = (ph ? 2 * ta + 1 : 2 * ta) * 5 + (pw ? 2 * tb + 1 : 2 * tb);

    if (tid < 128) {
        int y = gi.pi + da, xx = gi.pj + db;
        bool valid = ((unsigned)y < 28u) && ((unsigned)xx < 28u);
        const __half* src = g_xh + (valid ? ((gi.pb + y * 28 + xx) * CIn + kc * 32) : 0);
        int ss = valid ? 16 : 0;
        uint32_t abase = sb + gi.a_off;
#pragma unroll
        for (int c4 = 0; c4 < 4; ++c4) cpa16(abase + c4 * 16u, src + c4 * 8, ss);
    }
    {
        int img0 = (tap * 32 + kc * 2 + gi.ws0) * 4 + ntile;
        cpa16(sb + BOFF + gi.ws0 * 4096u + gi.wq0 * 16u, g_wA + img0 * 2048 + gi.wq0 * 8, 16);
        int img1 = (tap * 32 + kc * 2 + gi.ws1) * 4 + ntile;
        cpa16(sb + BOFF + gi.ws1 * 4096u + gi.wq1 * 16u, g_wA + img1 * 2048 + gi.wq1 * 8, 16);
    }
}

// ---------------- chunk issue: convB ----------------------------------------
__device__ __forceinline__ void issueB(uint32_t sb, int cc, const GInv& gi,
                                       int ntile, int tid)
{
    int tapi = cc >> 3, kc = cc & 7;
    int da = tapi / 3 - 1, db = tapi % 3 - 1;

    if (tid < 128) {
        int y = gi.pi + da, xx = gi.pj + db;
        bool valid = ((unsigned)y < 56u) && ((unsigned)xx < 56u);
        const __half* src = g_t1h + (valid ? ((gi.pb + y * 56 + xx) * COc + kc * 32) : 0);
        int ss = valid ? 16 : 0;
        uint32_t abase = sb + gi.a_off;
#pragma unroll
        for (int c4 = 0; c4 < 4; ++c4) cpa16(abase + c4 * 16u, src + c4 * 8, ss);
    }
    {
        int img0 = (tapi * 16 + kc * 2 + gi.ws0) * 2 + ntile;
        cpa16(sb + BOFF + gi.ws0 * 4096u + gi.wq0 * 16u, g_wB + img0 * 2048 + gi.wq0 * 8, 16);
        int img1 = (tapi * 16 + kc * 2 + gi.ws1) * 2 + ntile;
        cpa16(sb + BOFF + gi.ws1 * 4096u + gi.wq1 * 16u, g_wB + img1 * 2048 + gi.wq1 * 8, 16);
    }
}

// ---------------- GEMM A: conv1 / shortcut ----------------------------------
__global__ __launch_bounds__(256, 2)
void convA_mma(const float* __restrict__ g1, const float* __restrict__ b1,
               const float* __restrict__ m1, const float* __restrict__ v1,
               const float* __restrict__ gs, const float* __restrict__ bs,
               const float* __restrict__ ms, const float* __restrict__ vs)
{
    extern __shared__ __align__(16) uint8_t dsm[];
    const uint32_t sb0 = smem_u32(dsm);
    const uint32_t mb  = sb0 + MBAR_OFF;
    const int tid = threadIdx.x, lane = tid & 31, wid = tid >> 5;
    const int wm = wid >> 2, wn = wid & 3;
    const int m0 = blockIdx.x * 128, ntile = blockIdx.y;
    const int par = blockIdx.z;
    const int ph = par >> 1, pw = par & 1;
    const int nTa = ph ? 2 : 3, nTb = pw ? 2 : 3;
    const int C = nTa * nTb * 16;

    if (tid < NSTAGE) { mb_init(FULLB(tid), 256); mb_init(EMPTYB(tid), 256); }
    __syncthreads();

    // loop-invariant gather state
    GInv gi;
    {
        int m = m0 + (tid < 128 ? tid : 0);
        int b = m / 784, sp = m - b * 784;
        gi.pb = b * 784;
        gi.pi = sp / 28;
        gi.pj = sp - gi.pi * 28;
        gi.a_off = (uint32_t)tid * 80u;
        int q0 = tid * 2, q1 = tid * 2 + 1;
        gi.ws0 = q0 >> 8; gi.wq0 = q0 & 255;
        gi.ws1 = q1 >> 8; gi.wq1 = q1 & 255;
    }

    float acc[4][4][4];
#pragma unroll
    for (int a = 0; a < 4; ++a)
#pragma unroll
        for (int b = 0; b < 4; ++b)
#pragma unroll
            for (int e = 0; e < 4; ++e) acc[a][b][e] = 0.f;

    // prologue: fill stages 0..2
#pragma unroll
    for (int p = 0; p < 3; ++p) {
        issueA(sb0 + p * STAGE_BYTES, p, gi, ntile, ph, pw, nTb, tid);
        cp_arrive(FULLB(p));
    }

    int s = 0, pf = 0;        // consume stage/parity
    int s2 = 3, pe = 1;       // issue stage / empty parity
    for (int cc = 0; cc < C; ++cc) {
        int c2 = cc + 3;
        if (c2 < C) {
            if (c2 >= NSTAGE) mb_wait(EMPTYB(s2), pe);
            issueA(sb0 + s2 * STAGE_BYTES, c2, gi, ntile, ph, pw, nTb, tid);
            cp_arrive(FULLB(s2));
            if (++s2 == NSTAGE) { s2 = 0; pe ^= 1; }
        }
        mb_wait(FULLB(s), pf);
        const uint32_t SBc = sb0 + s * STAGE_BYTES;
        MMA_STAGE(SBc)
        mb_arrive(EMPTYB(s));
        if (++s == NSTAGE) { s = 0; pf ^= 1; }
    }
    __syncthreads();

    const int n0 = ntile * 128;
    if (ntile < 2) {
        // ---- t1 branch: BN + ReLU, store single fp16, channel-last ----------
        float es[4][2], eb[4][2];
#pragma unroll
        for (int nfl = 0; nfl < 4; ++nfl)
#pragma unroll
            for (int t = 0; t < 2; ++t) {
                int oc = n0 + wn * 32 + nfl * 8 + 2 * (lane & 3) + t;
                float sv = g1[oc] * rsqrtf(v1[oc] + 1e-5f);
                es[nfl][t] = sv;
                eb[nfl][t] = b1[oc] - m1[oc] * sv;
            }
#pragma unroll
        for (int mfl = 0; mfl < 4; ++mfl)
#pragma unroll
            for (int eh = 0; eh < 2; ++eh) {
                int ml = wm * 64 + mfl * 16 + (lane >> 2) + 8 * eh;
                int m = m0 + ml;
                int b = m / 784, sp = m - b * 784;
                int i = sp / 28, j = sp - i * 28;
                int oh = 2 * i + ph, ow = 2 * j + pw;
                int base = (b * 3136 + oh * 56 + ow) * COc + n0 + wn * 32 + 2 * (lane & 3);
#pragma unroll
                for (int nfl = 0; nfl < 4; ++nfl) {
                    float v0 = fmaxf(acc[mfl][nfl][eh * 2 + 0] * es[nfl][0] + eb[nfl][0], 0.f);
                    float v1v = fmaxf(acc[mfl][nfl][eh * 2 + 1] * es[nfl][1] + eb[nfl][1], 0.f);
                    __half2 h2;
                    h2.x = __float2half(v0);
                    h2.y = __float2half(v1v);
                    *(__half2*)(g_t1h + base + nfl * 8) = h2;
                }
            }
    } else {
        // ---- shortcut branch: smem transpose, BN, NCHW scatter --------------
        float* stage = (float*)dsm;
        for (int p = 0; p < 2; ++p) {
            __syncthreads();
            if ((wn >> 1) == p) {
#pragma unroll
                for (int mfl = 0; mfl < 4; ++mfl)
#pragma unroll
                    for (int nfl = 0; nfl < 4; ++nfl)
#pragma unroll
                        for (int e = 0; e < 4; ++e) {
                            int nlrel = (wn & 1) * 32 + nfl * 8 + 2 * (lane & 3) + (e & 1);
                            int ml    = wm * 64 + mfl * 16 + (lane >> 2) + 8 * (e >> 1);
                            stage[nlrel * 132 + ml] = acc[mfl][nfl][e];
                        }
            }
            __syncthreads();
#pragma unroll
            for (int rr = 0; rr < 8; ++rr) {
                int row = wid * 8 + rr;
                int c   = n0 - COc + p * 64 + row;
                float sv  = gs[c] * rsqrtf(vs[c] + 1e-5f);
                float ebv = bs[c] - ms[c] * sv;
                float4 f = *(const float4*)(stage + row * 132 + lane * 4);
                float fv[4] = {f.x, f.y, f.z, f.w};
#pragma unroll
                for (int q = 0; q < 4; ++q) {
                    int m = m0 + lane * 4 + q;
                    int b = m / 784, sp = m - b * 784;
                    int i = sp / 28, j = sp - i * 28;
                    int oh = 2 * i + ph, ow = 2 * j + pw;
                    g_scf[((b * COc + c) * 56 + oh) * 56 + ow] = fv[q] * sv + ebv;
                }
            }
        }
    }
}

// ---------------- GEMM B: conv2 + BN2 + shortcut + ReLU ---------------------
__global__ __launch_bounds__(256, 2)
void convB_mma(const float* __restrict__ g2, const float* __restrict__ b2,
               const float* __restrict__ m2, const float* __restrict__ v2,
               float* __restrict__ out)
{
    extern __shared__ __align__(16) uint8_t dsm[];
    const uint32_t sb0 = smem_u32(dsm);
    const uint32_t mb  = sb0 + MBAR_OFF;
    const int tid = threadIdx.x, lane = tid & 31, wid = tid >> 5;
    const int wm = wid >> 2, wn = wid & 3;
    const int m0 = blockIdx.x * 128, ntile = blockIdx.y;
    const int C = 72;

    if (tid < NSTAGE) { mb_init(FULLB(tid), 256); mb_init(EMPTYB(tid), 256); }
    __syncthreads();

    GInv gi;
    {
        int m = m0 + (tid < 128 ? tid : 0);
        int b = m / 3136, sp = m - b * 3136;
        gi.pb = b * 3136;
        gi.pi = sp / 56;
        gi.pj = sp - gi.pi * 56;
        gi.a_off = (uint32_t)tid * 80u;
        int q0 = tid * 2, q1 = tid * 2 + 1;
        gi.ws0 = q0 >> 8; gi.wq0 = q0 & 255;
        gi.ws1 = q1 >> 8; gi.wq1 = q1 & 255;
    }

    float acc[4][4][4];
#pragma unroll
    for (int a = 0; a < 4; ++a)
#pragma unroll
        for (int b = 0; b < 4; ++b)
#pragma unroll
            for (int e = 0; e < 4; ++e) acc[a][b][e] = 0.f;

#pragma unroll
    for (int p = 0; p < 3; ++p) {
        issueB(sb0 + p * STAGE_BYTES, p, gi, ntile, tid);
        cp_arrive(FULLB(p));
    }

    int s = 0, pf = 0;
    int s2 = 3, pe = 1;
    for (int cc = 0; cc < C; ++cc) {
        int c2 = cc + 3;
        if (c2 < C) {
            if (c2 >= NSTAGE) mb_wait(EMPTYB(s2), pe);
            issueB(sb0 + s2 * STAGE_BYTES, c2, gi, ntile, tid);
            cp_arrive(FULLB(s2));
            if (++s2 == NSTAGE) { s2 = 0; pe ^= 1; }
        }
        mb_wait(FULLB(s), pf);
        const uint32_t SBc = sb0 + s * STAGE_BYTES;
        MMA_STAGE(SBc)
        mb_arrive(EMPTYB(s));
        if (++s == NSTAGE) { s = 0; pf ^= 1; }
    }
    __syncthreads();

    float* stage = (float*)dsm;
    const int n0 = ntile * 128;
    for (int p = 0; p < 2; ++p) {
        __syncthreads();
        if ((wn >> 1) == p) {
#pragma unroll
            for (int mfl = 0; mfl < 4; ++mfl)
#pragma unroll
                for (int nfl = 0; nfl < 4; ++nfl)
#pragma unroll
                    for (int e = 0; e < 4; ++e) {
                        int nlrel = (wn & 1) * 32 + nfl * 8 + 2 * (lane & 3) + (e & 1);
                        int ml    = wm * 64 + mfl * 16 + (lane >> 2) + 8 * (e >> 1);
                        stage[nlrel * 132 + ml] = acc[mfl][nfl][e];
                    }
        }
        __syncthreads();
#pragma unroll
        for (int rr = 0; rr < 8; ++rr) {
            int row = wid * 8 + rr;
            int oc  = n0 + p * 64 + row;
            float sv = g2[oc] * rsqrtf(v2[oc] + 1e-5f);
            float eb = b2[oc] - m2[oc] * sv;
            int m = m0 + lane * 4;
            int b = m / 3136, sp = m - b * 3136;
            int idx = (b * COc + oc) * 3136 + sp;
            float4 f  = *(const float4*)(stage + row * 132 + lane * 4);
            float4 sc = *(const float4*)(g_scf + idx);
            float4 o;
            o.x = fmaxf(f.x * sv + eb + sc.x, 0.f);
            o.y = fmaxf(f.y * sv + eb + sc.y, 0.f);
            o.z = fmaxf(f.z * sv + eb + sc.z, 0.f);
            o.w = fmaxf(f.w * sv + eb + sc.w, 0.f);
            *(float4*)(out + idx) = o;
        }
    }
}

// ---------------------------------------------------------------------------
extern "C" void kernel_launch(void* const* d_in, const int* in_sizes, int n_in,
                              void* d_out, int out_size)
{
    const float* x   = (const float*)d_in[0];
    const float* w1  = (const float*)d_in[1];
    const float* g1  = (const float*)d_in[2];
    const float* b1  = (const float*)d_in[3];
    const float* m1  = (const float*)d_in[4];
    const float* v1  = (const float*)d_in[5];
    const float* w2  = (const float*)d_in[6];
    const float* g2  = (const float*)d_in[7];
    const float* b2  = (const float*)d_in[8];
    const float* m2  = (const float*)d_in[9];
    const float* v2  = (const float*)d_in[10];
    const float* wsc = (const float*)d_in[11];
    const float* gs  = (const float*)d_in[12];
    const float* bs  = (const float*)d_in[13];
    const float* ms  = (const float*)d_in[14];
    const float* vs  = (const float*)d_in[15];
    float* out = (float*)d_out;

    static int configured = 0;
    if (!configured) {
        cudaFuncSetAttribute(convA_mma, cudaFuncAttributeMaxDynamicSharedMemorySize, SMEM_BYTES);
        cudaFuncSetAttribute(convB_mma, cudaFuncAttributeMaxDynamicSharedMemorySize, SMEM_BYTES);
        configured = 1;
    }

    prep_all<<<NXBLK + 25600, 256>>>(x, w1, wsc, w2);

    dim3 gA(98, 4, 4);
    convA_mma<<<gA, 256, SMEM_BYTES>>>(g1, b1, m1, v1, gs, bs, ms, vs);

    dim3 gB(392, 2);
    convB_mma<<<gB, 256, SMEM_BYTES>>>(g2, b2, m2, v2, out);
}

// round 17
// speedup vs baseline: 6.7619x; 1.0422x over previous
#include <cuda_runtime.h>
#include <cuda_fp16.h>
#include <stdint.h>

#define CIn 512
#define COc 256
#define NB  16

// ---------------- device scratch (allocation-free) --------------------------
__device__ __half g_xh [NB * 784 * CIn];       // x channel-last, fp16
__device__ __half g_t1h[NB * 3136 * COc];      // t1 channel-last, fp16
__device__ float  g_scf[NB * COc * 3136];      // shortcut, NCHW fp32
__device__ __half g_wA [25 * 32 * 4 * 2048];   // frag-order weights (fp16)
__device__ __half g_wB [9 * 16 * 2 * 2048];

// ---------------- smem stage layout (A-only, K=32 per stage) -----------------
// A [0, 10240) : 128 rows x 64B data in 80B stride
#define STAGE_BYTES 10240
#define NSTAGE 5
#define MBAR_OFF (NSTAGE * STAGE_BYTES)        // 51200
#define SMEM_BYTES (MBAR_OFF + 128)

// ---------------- helpers ---------------------------------------------------
__device__ __forceinline__ uint32_t smem_u32(const void* p) {
    uint32_t a;
    asm("{ .reg .u64 t; cvta.to.shared.u64 t, %1; cvt.u32.u64 %0, t; }"
        : "=r"(a) : "l"(p));
    return a;
}
__device__ __forceinline__ void cpa16(uint32_t dst, const void* src, int srcsize) {
    asm volatile("cp.async.cg.shared.global [%0], [%1], 16, %2;"
                 :: "r"(dst), "l"(src), "r"(srcsize));
}
__device__ __forceinline__ void mb_init(uint32_t a, uint32_t cnt) {
    asm volatile("mbarrier.init.shared.b64 [%0], %1;" :: "r"(a), "r"(cnt) : "memory");
}
__device__ __forceinline__ void mb_arrive(uint32_t a) {
    asm volatile("{\n\t.reg .b64 t;\n\tmbarrier.arrive.shared.b64 t, [%0];\n\t}"
                 :: "r"(a) : "memory");
}
__device__ __forceinline__ void cp_arrive(uint32_t a) {
    asm volatile("cp.async.mbarrier.arrive.noinc.shared.b64 [%0];" :: "r"(a) : "memory");
}
__device__ __forceinline__ void mb_wait(uint32_t a, uint32_t par) {
    uint32_t done;
    do {
        asm volatile(
            "{\n\t.reg .pred p;\n\t"
            "mbarrier.test_wait.parity.shared.b64 p, [%1], %2;\n\t"
            "selp.b32 %0, 1, 0, p;\n\t}"
            : "=r"(done) : "r"(a), "r"(par) : "memory");
        if (!done) __nanosleep(20);
    } while (!done);
}
__device__ __forceinline__ void mma16816h(float* c, const uint32_t* a, const uint32_t* b) {
    asm volatile(
        "mma.sync.aligned.m16n8k16.row.col.f32.f16.f16.f32 "
        "{%0,%1,%2,%3},{%4,%5,%6,%7},{%8,%9},{%0,%1,%2,%3};"
        : "+f"(c[0]), "+f"(c[1]), "+f"(c[2]), "+f"(c[3])
        : "r"(a[0]), "r"(a[1]), "r"(a[2]), "r"(a[3]), "r"(b[0]), "r"(b[1]));
}
__device__ __forceinline__ void ldg64nc(uint32_t& r0, uint32_t& r1, const void* p) {
    asm volatile("ld.global.nc.v2.u32 {%0,%1}, [%2];"
                 : "=r"(r0), "=r"(r1) : "l"(p));
}
__device__ __forceinline__ int bfrag_idx(int nf, int n, int kk) {
    int lane = n * 4 + ((kk & 7) >> 1);
    return nf * 128 + lane * 4 + (kk >> 3) * 2 + (kk & 1);
}

// ---------------- fused prep: channel-last fp16 x + frag-order weights ------
#define NXBLK 6400
__global__ void prep_all(const float* __restrict__ x,  const float* __restrict__ w1,
                         const float* __restrict__ wsc, const float* __restrict__ w2)
{
    __shared__ float tile[32][33];
    if (blockIdx.x < NXBLK) {
        int bid = blockIdx.x;
        int st  = (bid % 25) * 32;
        int cib = ((bid / 25) & 15) * 32;
        int b   = bid / 400;
        const int tx = threadIdx.x & 31, ty = threadIdx.x >> 5;
#pragma unroll
        for (int i = 0; i < 4; ++i) {
            int ci = i * 8 + ty;
            int s  = st + tx;
            float v = 0.f;
            if (s < 784) v = x[(b * CIn + cib + ci) * 784 + s];
            tile[ci][tx] = v;
        }
        __syncthreads();
#pragma unroll
        for (int i = 0; i < 4; ++i) {
            int s = st + i * 8 + ty;
            if (s < 784)
                g_xh[(b * 784 + s) * CIn + cib + tx] = __float2half(tile[tx][i * 8 + ty]);
        }
    } else {
        int idx = (blockIdx.x - NXBLK) * 256 + threadIdx.x;
        const int nA  = 25 * CIn * 512;
        const int nBw = 9 * COc * COc;
        if (idx < nA) {
            int tap = idx % 25, rest = idx / 25;
            int ci = rest & 511, oc = rest >> 9;
            float v = (oc < COc) ? w1[(oc * CIn + ci) * 25 + tap]
                                 : wsc[((oc - COc) * CIn + ci) * 25 + tap];
            int e = ((tap * 32 + (ci >> 4)) * 4 + (oc >> 7)) * 2048
                  + bfrag_idx((oc & 127) >> 3, oc & 7, ci & 15);
            g_wA[e] = __float2half(v);
        }
        if (idx < nBw) {
            int tap = idx % 9, rest = idx / 9;
            int ci = rest & 255, oc = rest >> 8;
            float v = w2[(oc * COc + ci) * 9 + tap];
            int e = ((tap * 16 + (ci >> 4)) * 2 + (oc >> 7)) * 2048
                  + bfrag_idx((oc & 127) >> 3, oc & 7, ci & 15);
            g_wB[e] = __float2half(v);
        }
    }
}

// ---------------- MMA on one ready stage (B from registers) -----------------
#define MMA_STAGE(SB)                                                           \
{                                                                               \
    _Pragma("unroll")                                                           \
    for (int s = 0; s < 2; ++s) {                                               \
        _Pragma("unroll")                                                       \
        for (int mfl = 0; mfl < 4; ++mfl) {                                     \
            uint32_t aa = (SB) + (wm * 64 + mfl * 16 + (lane & 15)) * 80u       \
                        + (s * 2 + (lane >> 4)) * 16u;                          \
            uint32_t ah[4];                                                     \
            asm volatile("ldmatrix.sync.aligned.m8n8.x4.shared.b16 {%0,%1,%2,%3}, [%4];" \
                : "=r"(ah[0]), "=r"(ah[1]), "=r"(ah[2]), "=r"(ah[3]) : "r"(aa)); \
            _Pragma("unroll")                                                   \
            for (int nfl = 0; nfl < 4; ++nfl)                                   \
                mma16816h(acc[mfl][nfl], ah, bfr[s][nfl]);                      \
        }                                                                       \
    }                                                                           \
}

// mbar addresses: full[s] = mb + s*16, empty[s] = mb + s*16 + 8
#define FULLB(s)  (mb + (uint32_t)(s) * 16u)
#define EMPTYB(s) (mb + (uint32_t)(s) * 16u + 8u)

// Per-thread loop-invariant gather state
struct GInv {
    int pb;          // batch * spatial_size
    int pi, pj;      // spatial coords
    uint32_t a_off;  // A smem offset within stage (tid*80)
};

// ---------------- B register loads (direct from gmem, L2-hot) ---------------
__device__ __forceinline__ void loadB_A(uint32_t bfr[2][4][2], int cc, int ntile,
                                        int ph, int pw, int nTb, int boff)
{
    int tapi = cc >> 4, kc = cc & 15;
    int ta, tb;
    if (nTb == 2) { ta = tapi >> 1; tb = tapi & 1; }
    else          { ta = tapi / 3;  tb = tapi % 3; }
    int tap = (ph ? 2 * ta + 1 : 2 * ta) * 5 + (pw ? 2 * tb + 1 : 2 * tb);
#pragma unroll
    for (int s = 0; s < 2; ++s) {
        const __half* base = g_wA + ((tap * 32 + kc * 2 + s) * 4 + ntile) * 2048 + boff;
#pragma unroll
        for (int nfl = 0; nfl < 4; ++nfl)
            ldg64nc(bfr[s][nfl][0], bfr[s][nfl][1], base + nfl * 128);
    }
}
__device__ __forceinline__ void loadB_B(uint32_t bfr[2][4][2], int cc, int ntile,
                                        int boff)
{
    int tapi = cc >> 3, kc = cc & 7;
#pragma unroll
    for (int s = 0; s < 2; ++s) {
        const __half* base = g_wB + ((tapi * 16 + kc * 2 + s) * 2 + ntile) * 2048 + boff;
#pragma unroll
        for (int nfl = 0; nfl < 4; ++nfl)
            ldg64nc(bfr[s][nfl][0], bfr[s][nfl][1], base + nfl * 128);
    }
}

// ---------------- chunk issue: convA (A gather only) ------------------------
__device__ __forceinline__ void issueA(uint32_t sb, int cc, const GInv& gi,
                                       int ph, int pw, int nTb, int tid)
{
    int tapi = cc >> 4, kc = cc & 15;
    int ta, tb;
    if (nTb == 2) { ta = tapi >> 1; tb = tapi & 1; }
    else          { ta = tapi / 3;  tb = tapi % 3; }
    int da = ph ? ta : ta - 1;
    int db = pw ? tb : tb - 1;

    if (tid < 128) {
        int y = gi.pi + da, xx = gi.pj + db;
        bool valid = ((unsigned)y < 28u) && ((unsigned)xx < 28u);
        const __half* src = g_xh + (valid ? ((gi.pb + y * 28 + xx) * CIn + kc * 32) : 0);
        int ss = valid ? 16 : 0;
        uint32_t abase = sb + gi.a_off;
#pragma unroll
        for (int c4 = 0; c4 < 4; ++c4) cpa16(abase + c4 * 16u, src + c4 * 8, ss);
    }
}

// ---------------- chunk issue: convB ----------------------------------------
__device__ __forceinline__ void issueB(uint32_t sb, int cc, const GInv& gi, int tid)
{
    int tapi = cc >> 3, kc = cc & 7;
    int da = tapi / 3 - 1, db = tapi % 3 - 1;

    if (tid < 128) {
        int y = gi.pi + da, xx = gi.pj + db;
        bool valid = ((unsigned)y < 56u) && ((unsigned)xx < 56u);
        const __half* src = g_t1h + (valid ? ((gi.pb + y * 56 + xx) * COc + kc * 32) : 0);
        int ss = valid ? 16 : 0;
        uint32_t abase = sb + gi.a_off;
#pragma unroll
        for (int c4 = 0; c4 < 4; ++c4) cpa16(abase + c4 * 16u, src + c4 * 8, ss);
    }
}

// ---------------- GEMM A: conv1 / shortcut ----------------------------------
__global__ __launch_bounds__(256, 2)
void convA_mma(const float* __restrict__ g1, const float* __restrict__ b1,
               const float* __restrict__ m1, const float* __restrict__ v1,
               const float* __restrict__ gs, const float* __restrict__ bs,
               const float* __restrict__ ms, const float* __restrict__ vs)
{
    extern __shared__ __align__(16) uint8_t dsm[];
    const uint32_t sb0 = smem_u32(dsm);
    const uint32_t mb  = sb0 + MBAR_OFF;
    const int tid = threadIdx.x, lane = tid & 31, wid = tid >> 5;
    const int wm = wid >> 2, wn = wid & 3;
    const int m0 = blockIdx.x * 128, ntile = blockIdx.y;
    const int par = blockIdx.z;
    const int ph = par >> 1, pw = par & 1;
    const int nTa = ph ? 2 : 3, nTb = pw ? 2 : 3;
    const int C = nTa * nTb * 16;
    const int boff = (wn * 4) * 128 + lane * 4;   // B frag gmem offset (halfs)

    if (tid < NSTAGE) { mb_init(FULLB(tid), 256); mb_init(EMPTYB(tid), 256); }
    __syncthreads();

    GInv gi;
    {
        int m = m0 + (tid < 128 ? tid : 0);
        int b = m / 784, sp = m - b * 784;
        gi.pb = b * 784;
        gi.pi = sp / 28;
        gi.pj = sp - gi.pi * 28;
        gi.a_off = (uint32_t)tid * 80u;
    }

    float acc[4][4][4];
#pragma unroll
    for (int a = 0; a < 4; ++a)
#pragma unroll
        for (int b = 0; b < 4; ++b)
#pragma unroll
            for (int e = 0; e < 4; ++e) acc[a][b][e] = 0.f;

    uint32_t bfr[2][4][2];
    loadB_A(bfr, 0, ntile, ph, pw, nTb, boff);

    // prologue: fill stages 0..2
#pragma unroll
    for (int p = 0; p < 3; ++p) {
        issueA(sb0 + p * STAGE_BYTES, p, gi, ph, pw, nTb, tid);
        cp_arrive(FULLB(p));
    }

    int s = 0, pf = 0;        // consume stage/parity
    int s2 = 3, pe = 1;       // issue stage / empty parity
    for (int cc = 0; cc < C; ++cc) {
        int c2 = cc + 3;
        if (c2 < C) {
            if (c2 >= NSTAGE) mb_wait(EMPTYB(s2), pe);
            issueA(sb0 + s2 * STAGE_BYTES, c2, gi, ph, pw, nTb, tid);
            cp_arrive(FULLB(s2));
            if (++s2 == NSTAGE) { s2 = 0; pe ^= 1; }
        }
        mb_wait(FULLB(s), pf);
        const uint32_t SBc = sb0 + s * STAGE_BYTES;
        MMA_STAGE(SBc)
        mb_arrive(EMPTYB(s));
        if (++s == NSTAGE) { s = 0; pf ^= 1; }
        if (cc + 1 < C) loadB_A(bfr, cc + 1, ntile, ph, pw, nTb, boff);
    }
    __syncthreads();

    const int n0 = ntile * 128;
    if (ntile < 2) {
        // ---- t1 branch: BN + ReLU, store single fp16, channel-last ----------
        float es[4][2], eb[4][2];
#pragma unroll
        for (int nfl = 0; nfl < 4; ++nfl)
#pragma unroll
            for (int t = 0; t < 2; ++t) {
                int oc = n0 + wn * 32 + nfl * 8 + 2 * (lane & 3) + t;
                float sv = g1[oc] * rsqrtf(v1[oc] + 1e-5f);
                es[nfl][t] = sv;
                eb[nfl][t] = b1[oc] - m1[oc] * sv;
            }
#pragma unroll
        for (int mfl = 0; mfl < 4; ++mfl)
#pragma unroll
            for (int eh = 0; eh < 2; ++eh) {
                int ml = wm * 64 + mfl * 16 + (lane >> 2) + 8 * eh;
                int m = m0 + ml;
                int b = m / 784, sp = m - b * 784;
                int i = sp / 28, j = sp - i * 28;
                int oh = 2 * i + ph, ow = 2 * j + pw;
                int base = (b * 3136 + oh * 56 + ow) * COc + n0 + wn * 32 + 2 * (lane & 3);
#pragma unroll
                for (int nfl = 0; nfl < 4; ++nfl) {
                    float v0 = fmaxf(acc[mfl][nfl][eh * 2 + 0] * es[nfl][0] + eb[nfl][0], 0.f);
                    float v1v = fmaxf(acc[mfl][nfl][eh * 2 + 1] * es[nfl][1] + eb[nfl][1], 0.f);
                    __half2 h2;
                    h2.x = __float2half(v0);
                    h2.y = __float2half(v1v);
                    *(__half2*)(g_t1h + base + nfl * 8) = h2;
                }
            }
    } else {
        // ---- shortcut branch: smem transpose, BN, NCHW scatter --------------
        float* stage = (float*)dsm;
        for (int p = 0; p < 2; ++p) {
            __syncthreads();
            if ((wn >> 1) == p) {
#pragma unroll
                for (int mfl = 0; mfl < 4; ++mfl)
#pragma unroll
                    for (int nfl = 0; nfl < 4; ++nfl)
#pragma unroll
                        for (int e = 0; e < 4; ++e) {
                            int nlrel = (wn & 1) * 32 + nfl * 8 + 2 * (lane & 3) + (e & 1);
                            int ml    = wm * 64 + mfl * 16 + (lane >> 2) + 8 * (e >> 1);
                            stage[nlrel * 132 + ml] = acc[mfl][nfl][e];
                        }
            }
            __syncthreads();
#pragma unroll
            for (int rr = 0; rr < 8; ++rr) {
                int row = wid * 8 + rr;
                int c   = n0 - COc + p * 64 + row;
                float sv  = gs[c] * rsqrtf(vs[c] + 1e-5f);
                float ebv = bs[c] - ms[c] * sv;
                float4 f = *(const float4*)(stage + row * 132 + lane * 4);
                float fv[4] = {f.x, f.y, f.z, f.w};
#pragma unroll
                for (int q = 0; q < 4; ++q) {
                    int m = m0 + lane * 4 + q;
                    int b = m / 784, sp = m - b * 784;
                    int i = sp / 28, j = sp - i * 28;
                    int oh = 2 * i + ph, ow = 2 * j + pw;
                    g_scf[((b * COc + c) * 56 + oh) * 56 + ow] = fv[q] * sv + ebv;
                }
            }
        }
    }
}

// ---------------- GEMM B: conv2 + BN2 + shortcut + ReLU ---------------------
__global__ __launch_bounds__(256, 2)
void convB_mma(const float* __restrict__ g2, const float* __restrict__ b2,
               const float* __restrict__ m2, const float* __restrict__ v2,
               float* __restrict__ out)
{
    extern __shared__ __align__(16) uint8_t dsm[];
    const uint32_t sb0 = smem_u32(dsm);
    const uint32_t mb  = sb0 + MBAR_OFF;
    const int tid = threadIdx.x, lane = tid & 31, wid = tid >> 5;
    const int wm = wid >> 2, wn = wid & 3;
    const int m0 = blockIdx.x * 128, ntile = blockIdx.y;
    const int C = 72;
    const int boff = (wn * 4) * 128 + lane * 4;

    if (tid < NSTAGE) { mb_init(FULLB(tid), 256); mb_init(EMPTYB(tid), 256); }
    __syncthreads();

    GInv gi;
    {
        int m = m0 + (tid < 128 ? tid : 0);
        int b = m / 3136, sp = m - b * 3136;
        gi.pb = b * 3136;
        gi.pi = sp / 56;
        gi.pj = sp - gi.pi * 56;
        gi.a_off = (uint32_t)tid * 80u;
    }

    float acc[4][4][4];
#pragma unroll
    for (int a = 0; a < 4; ++a)
#pragma unroll
        for (int b = 0; b < 4; ++b)
#pragma unroll
            for (int e = 0; e < 4; ++e) acc[a][b][e] = 0.f;

    uint32_t bfr[2][4][2];
    loadB_B(bfr, 0, ntile, boff);

#pragma unroll
    for (int p = 0; p < 3; ++p) {
        issueB(sb0 + p * STAGE_BYTES, p, gi, tid);
        cp_arrive(FULLB(p));
    }

    int s = 0, pf = 0;
    int s2 = 3, pe = 1;
    for (int cc = 0; cc < C; ++cc) {
        int c2 = cc + 3;
        if (c2 < C) {
            if (c2 >= NSTAGE) mb_wait(EMPTYB(s2), pe);
            issueB(sb0 + s2 * STAGE_BYTES, c2, gi, tid);
            cp_arrive(FULLB(s2));
            if (++s2 == NSTAGE) { s2 = 0; pe ^= 1; }
        }
        mb_wait(FULLB(s), pf);
        const uint32_t SBc = sb0 + s * STAGE_BYTES;
        MMA_STAGE(SBc)
        mb_arrive(EMPTYB(s));
        if (++s == NSTAGE) { s = 0; pf ^= 1; }
        if (cc + 1 < C) loadB_B(bfr, cc + 1, ntile, boff);
    }
    __syncthreads();

    float* stage = (float*)dsm;
    const int n0 = ntile * 128;
    for (int p = 0; p < 2; ++p) {
        __syncthreads();
        if ((wn >> 1) == p) {
#pragma unroll
            for (int mfl = 0; mfl < 4; ++mfl)
#pragma unroll
                for (int nfl = 0; nfl < 4; ++nfl)
#pragma unroll
                    for (int e = 0; e < 4; ++e) {
                        int nlrel = (wn & 1) * 32 + nfl * 8 + 2 * (lane & 3) + (e & 1);
                        int ml    = wm * 64 + mfl * 16 + (lane >> 2) + 8 * (e >> 1);
                        stage[nlrel * 132 + ml] = acc[mfl][nfl][e];
                    }
        }
        __syncthreads();
#pragma unroll
        for (int rr = 0; rr < 8; ++rr) {
            int row = wid * 8 + rr;
            int oc  = n0 + p * 64 + row;
            float sv = g2[oc] * rsqrtf(v2[oc] + 1e-5f);
            float eb = b2[oc] - m2[oc] * sv;
            int m = m0 + lane * 4;
            int b = m / 3136, sp = m - b * 3136;
            int idx = (b * COc + oc) * 3136 + sp;
            float4 f  = *(const float4*)(stage + row * 132 + lane * 4);
            float4 sc = *(const float4*)(g_scf + idx);
            float4 o;
            o.x = fmaxf(f.x * sv + eb + sc.x, 0.f);
            o.y = fmaxf(f.y * sv + eb + sc.y, 0.f);
            o.z = fmaxf(f.z * sv + eb + sc.z, 0.f);
            o.w = fmaxf(f.w * sv + eb + sc.w, 0.f);
            *(float4*)(out + idx) = o;
        }
    }
}

// ---------------------------------------------------------------------------
extern "C" void kernel_launch(void* const* d_in, const int* in_sizes, int n_in,
                              void* d_out, int out_size)
{
    const float* x   = (const float*)d_in[0];
    const float* w1  = (const float*)d_in[1];
    const float* g1  = (const float*)d_in[2];
    const float* b1  = (const float*)d_in[3];
    const float* m1  = (const float*)d_in[4];
    const float* v1  = (const float*)d_in[5];
    const float* w2  = (const float*)d_in[6];
    const float* g2  = (const float*)d_in[7];
    const float* b2  = (const float*)d_in[8];
    const float* m2  = (const float*)d_in[9];
    const float* v2  = (const float*)d_in[10];
    const float* wsc = (const float*)d_in[11];
    const float* gs  = (const float*)d_in[12];
    const float* bs  = (const float*)d_in[13];
    const float* ms  = (const float*)d_in[14];
    const float* vs  = (const float*)d_in[15];
    float* out = (float*)d_out;

    static int configured = 0;
    if (!configured) {
        cudaFuncSetAttribute(convA_mma, cudaFuncAttributeMaxDynamicSharedMemorySize, SMEM_BYTES);
        cudaFuncSetAttribute(convB_mma, cudaFuncAttributeMaxDynamicSharedMemorySize, SMEM_BYTES);
        configured = 1;
    }

    prep_all<<<NXBLK + 25600, 256>>>(x, w1, wsc, w2);

    dim3 gA(98, 4, 4);
    convA_mma<<<gA, 256, SMEM_BYTES>>>(g1, b1, m1, v1, gs, bs, ms, vs);

    dim3 gB(392, 2);
    convB_mma<<<gB, 256, SMEM_BYTES>>>(g2, b2, m2, v2, out);
}